// round 12
// baseline (speedup 1.0000x reference)
#include <cuda_runtime.h>

#define NB 32      // batch
#define NT 2048    // tokens
#define ND 1024    // d_token == n_heads*d_head
#define TS 16      // token splits in reduce
#define TOK (NT/TS)           // 128 tokens per reduce block
#define KS2 8      // GEMM K-splits (K-slice = 128 floats = 32 float4)
#define OT 64      // o-columns per GEMM block tile
#define RGRID 512  // reduce-role blocks (16 splits x 32 batch)
#define TGRID 128  // tail-role blocks (16 o-tiles x 8 K-splits)
#define GRID (RGRID + TGRID)

// Scratch (allocation-free: __device__ globals, zero-initialized)
__device__ float g_part[TS][NB * ND];     // reduce partials (2 MB)
__device__ float g_xc[KS2][NB * ND];      // GEMM1 K-split partials
__device__ float g_op[KS2][NB * ND];      // GEMM2 K-split partials
__device__ unsigned g_flag;               // reduce-done counter (reset by tail)
__device__ unsigned g_cnt[3];             // barrier arrive counters (self-reset)
__device__ unsigned g_rel[3];             // barrier release generations (monotone)

// ---------------------------------------------------------------------------
// Grid barrier among the TGRID tail blocks only (they are mutually
// co-resident once reduce blocks retire; reduce blocks never wait).
// ---------------------------------------------------------------------------
template <int GRID_N>
__device__ __forceinline__ void grid_bar(int i) {
    __syncthreads();
    if (threadIdx.x == 0) {
        volatile unsigned* rel = &g_rel[i];
        const unsigned gen = *rel;          // read BEFORE our arrive
        __threadfence();                    // publish this block's phase writes
        if (atomicAdd(&g_cnt[i], 1u) == GRID_N - 1) {
            g_cnt[i] = 0;                   // reset for next graph replay
            __threadfence();
            atomicAdd(&g_rel[i], 1u);       // release (monotone)
        } else {
            while (*rel == gen) { __nanosleep(32); }
        }
        __threadfence();
    }
    __syncthreads();
}

// ---------------------------------------------------------------------------
// helpers
// ---------------------------------------------------------------------------
__device__ __forceinline__ void ffma2(unsigned long long& d,
                                      unsigned long long a,
                                      unsigned long long b) {
    asm("fma.rn.f32x2 %0, %1, %2, %0;" : "+l"(d) : "l"(a), "l"(b));
}
__device__ __forceinline__ void lds_v2u64(unsigned long long& lo,
                                          unsigned long long& hi,
                                          unsigned addr) {
    asm volatile("ld.shared.v2.u64 {%0, %1}, [%2];"
                 : "=l"(lo), "=l"(hi) : "r"(addr));
}
__device__ __forceinline__ float hsum2(unsigned long long v) {
    float2 f;
    __builtin_memcpy(&f, &v, 8);
    return f.x + f.y;
}
__device__ __forceinline__ float4 ldcs4(const float4* p) {   // streaming load
    float4 v;
    asm volatile("ld.global.cs.v4.f32 {%0,%1,%2,%3}, [%4];"
                 : "=f"(v.x), "=f"(v.y), "=f"(v.z), "=f"(v.w) : "l"(p));
    return v;
}
__device__ __forceinline__ void cp16(unsigned smem_addr, const void* gptr) {
    asm volatile("cp.async.cg.shared.global [%0], [%1], 16;"
                 :: "r"(smem_addr), "l"(gptr));
}
#define CP_COMMIT() asm volatile("cp.async.commit_group;")
#define CP_WAIT0()  asm volatile("cp.async.wait_group 0;")

// ---------------------------------------------------------------------------
// GEMM compute core (proven R6-R11): As[b][d4] x Ws swizzled -> dst.
// 256 thr, tile 64o x 32b x 128K, f32x2 FFMA packed along K.
// ---------------------------------------------------------------------------
__device__ __forceinline__ void gemm_core(const float4* As, const float4* Ws,
                                          float* __restrict__ dst, int otile) {
    const int tid = threadIdx.x;
    const int ox = tid & 31;
    const int bp = tid >> 5;
    const unsigned asBase = (unsigned)__cvta_generic_to_shared(As);
    const unsigned wsBase = (unsigned)__cvta_generic_to_shared(Ws);

    unsigned long long acc[4][2];
    #pragma unroll
    for (int i = 0; i < 4; ++i) { acc[i][0] = 0ull; acc[i][1] = 0ull; }

    #pragma unroll 8
    for (int d4 = 0; d4 < 32; ++d4) {
        unsigned long long w0lo, w0hi, w1lo, w1hi;
        lds_v2u64(w0lo, w0hi, wsBase + (unsigned)((d4 * OT + ((ox + d4) & 63)) << 4));
        lds_v2u64(w1lo, w1hi, wsBase + (unsigned)((d4 * OT + ((ox + 32 + d4) & 63)) << 4));
        #pragma unroll
        for (int i = 0; i < 4; ++i) {
            unsigned long long alo, ahi;
            lds_v2u64(alo, ahi, asBase + (unsigned)((((4 * bp + i) * 32 + d4)) << 4));
            ffma2(acc[i][0], alo, w0lo);
            ffma2(acc[i][0], ahi, w0hi);
            ffma2(acc[i][1], alo, w1lo);
            ffma2(acc[i][1], ahi, w1hi);
        }
    }
    #pragma unroll
    for (int i = 0; i < 4; ++i) {
        const int b = 4 * bp + i;
        dst[b * ND + otile + ox]      = hsum2(acc[i][0]);
        dst[b * ND + otile + 32 + ox] = hsum2(acc[i][1]);
    }
}

// issue cp.async for one W tile (64o x 32d4, swizzled layout)
__device__ __forceinline__ void w_tile_cp(const float* __restrict__ W,
                                          float4* Ws, int otile, int kbase4) {
    const int tid = threadIdx.x;
    const int o = tid >> 5, d4 = tid & 31;
    const unsigned base = (unsigned)__cvta_generic_to_shared(Ws);
    #pragma unroll
    for (int r = 0; r < 8; ++r) {
        const int oo = o + r * 8;
        cp16(base + (unsigned)((d4 * OT + ((oo + d4) & 63)) << 4),
             reinterpret_cast<const float4*>(W) + (size_t)(otile + oo) * (ND / 4) + kbase4 + d4);
    }
}

// ---------------------------------------------------------------------------
// ONE kernel, role-split grid: 512 non-blocking reduce producers + 128
// persistent tail consumers. 48 KB smem, <=64 regs -> 4 blocks/SM.
// ---------------------------------------------------------------------------
__global__ void __launch_bounds__(256, 4) k_all(const float* __restrict__ x,
                                                const float* __restrict__ Wh,
                                                const float* __restrict__ Wp,
                                                const float* __restrict__ bias,
                                                float* __restrict__ out) {
    extern __shared__ float4 dynsm[];       // 3072 float4 = 48 KB
    const int blk = blockIdx.x;
    const int tid = threadIdx.x;

    if (blk < RGRID) {
        // ===== Reduce role: 128 tokens x 1024 d, publish partial, EXIT =====
        const int s = blk & 15, b = blk >> 4;
        const float4* xp = reinterpret_cast<const float4*>(x)
                         + ((size_t)b * NT + (size_t)s * TOK) * (ND / 4) + tid;
        float4 a0 = make_float4(0.f, 0.f, 0.f, 0.f);
        float4 a1 = make_float4(0.f, 0.f, 0.f, 0.f);
        float4 a2 = make_float4(0.f, 0.f, 0.f, 0.f);
        float4 a3 = make_float4(0.f, 0.f, 0.f, 0.f);
        #pragma unroll 2
        for (int t = 0; t < TOK; t += 4) {
            float4 v0 = ldcs4(xp + (size_t)t * (ND / 4));
            float4 v1 = ldcs4(xp + (size_t)(t + 1) * (ND / 4));
            float4 v2 = ldcs4(xp + (size_t)(t + 2) * (ND / 4));
            float4 v3 = ldcs4(xp + (size_t)(t + 3) * (ND / 4));
            a0.x += v0.x; a0.y += v0.y; a0.z += v0.z; a0.w += v0.w;
            a1.x += v1.x; a1.y += v1.y; a1.z += v1.z; a1.w += v1.w;
            a2.x += v2.x; a2.y += v2.y; a2.z += v2.z; a2.w += v2.w;
            a3.x += v3.x; a3.y += v3.y; a3.z += v3.z; a3.w += v3.w;
        }
        float4 r = make_float4(a0.x + a1.x + a2.x + a3.x,
                               a0.y + a1.y + a2.y + a3.y,
                               a0.z + a1.z + a2.z + a3.z,
                               a0.w + a1.w + a2.w + a3.w);
        reinterpret_cast<float4*>(g_part[s])[b * (ND / 4) + tid] = r;
        __syncthreads();
        if (tid == 0) { __threadfence(); atomicAdd(&g_flag, 1u); }
        return;                              // producers never wait
    }

    // ===== Tail role: 128 blocks =====
    float4* Ws = dynsm;                      // 2048 float4 = 32 KB
    float4* As = dynsm + 2048;               // 1024 float4 = 16 KB
    const int tb = blk - RGRID;              // 0..127
    const int otile  = (tb >> 3) * OT;
    const int kbase4 = (tb & 7) * 32;

    // Prefetch Wh tile — overlaps the concurrent reduce for resident blocks.
    w_tile_cp(Wh, Ws, otile, kbase4);
    CP_COMMIT();

    // Wait for all 512 reduce partials.
    if (tid == 0) {
        volatile unsigned* f = &g_flag;
        while (*f < RGRID) { __nanosleep(64); }
    }
    __syncthreads();
    __threadfence();    // acquire

    // Phase 1: fold16-fused A-load, then gemm0 -> g_xc[ks]
    {
        const float4* src = reinterpret_cast<const float4*>(g_part);
        #pragma unroll
        for (int k = 0; k < 4; ++k) {
            const int idx = tid + k * 256;   // 1024 = 32b x 32d4
            const int b = idx >> 5, d4 = idx & 31;
            float4 v = make_float4(0.f, 0.f, 0.f, 0.f);
            #pragma unroll
            for (int s = 0; s < TS; ++s) {
                float4 u = src[(s * NB + b) * (ND / 4) + kbase4 + d4];
                v.x += u.x; v.y += u.y; v.z += u.z; v.w += u.w;
            }
            As[idx] = v;
        }
    }
    CP_WAIT0();
    __syncthreads();
    gemm_core(As, Ws, g_xc[tb & 7], otile);
    __syncthreads();                         // everyone done reading Ws

    // Prefetch Wp into Ws — hidden under bar1 + fold8.
    w_tile_cp(Wp, Ws, otile, kbase4);
    CP_COMMIT();

    grid_bar<TGRID>(0);
    if (tb == 0 && tid == 0) g_flag = 0;     // all tail passed the wait; reset

    // Phase 2: fold8 A-load, gemm1 -> g_op[ks]
    {
        #pragma unroll
        for (int k = 0; k < 4; ++k) {
            const int idx = tid + k * 256;
            const int b = idx >> 5, d4 = idx & 31;
            float4 v = make_float4(0.f, 0.f, 0.f, 0.f);
            #pragma unroll
            for (int p = 0; p < KS2; ++p) {
                float4 u = reinterpret_cast<const float4*>(g_xc[p])[b * (ND / 4) + kbase4 + d4];
                v.x += u.x; v.y += u.y; v.z += u.z; v.w += u.w;
            }
            As[idx] = v;
        }
    }
    CP_WAIT0();
    __syncthreads();
    gemm_core(As, Ws, g_op[tb & 7], otile);
    grid_bar<TGRID>(1);

    // Phase 3: epilogue — out = fold(g_op,8) + bias (64 float4 / block)
    if (tid < 64) {
        const int i = tb * 64 + tid;
        const int c4 = i & (ND / 4 - 1);
        float4 acc = reinterpret_cast<const float4*>(bias)[c4];
        #pragma unroll
        for (int p = 0; p < KS2; ++p) {
            float4 v = reinterpret_cast<const float4*>(g_op[p])[i];
            acc.x += v.x; acc.y += v.y; acc.z += v.z; acc.w += v.w;
        }
        reinterpret_cast<float4*>(out)[i] = acc;
    }
}

// ---------------------------------------------------------------------------
extern "C" void kernel_launch(void* const* d_in, const int* in_sizes, int n_in,
                              void* d_out, int out_size) {
    const float* x  = (const float*)d_in[0];   // [32, 2048, 1024]
    const float* Wh = (const float*)d_in[1];   // [16, 64, 1024] -> flat [1024,1024]
    const float* Wp = (const float*)d_in[2];   // [1024, 1024]
    const float* bp = (const float*)d_in[3];   // [1024]
    float* out = (float*)d_out;                // [32, 1024]

    k_all<<<GRID, 256, 3072 * sizeof(float4)>>>(x, Wh, Wp, bp, out);
}

// round 13
// speedup vs baseline: 1.0430x; 1.0430x over previous
#include <cuda_runtime.h>

#define NB 32      // batch
#define NT 2048    // tokens
#define ND 1024    // d_token == n_heads*d_head
#define ND4 (ND/4)            // 256 float4 per row
#define TS 16      // token splits in reduce
#define TOK (NT/TS)           // 128 tokens per reduce block
#define RGRID 512  // reduce blocks (16 splits x 32 batch)
#define TGRID 128  // tail blocks, each owns 8 output columns, full K
#define OSTRIPE 8  // o-columns per tail block

// Scratch (allocation-free: __device__ globals, zero-initialized)
__device__ float g_part[TS][NB * ND];     // reduce partials (2 MB)
__device__ float g_xs[NB * ND];           // folded token sum (128 KB)
__device__ float g_xh[NB * ND];           // gemm0 output (full-K, final)
__device__ unsigned g_cnt[2];             // barrier arrive counters (self-reset)
__device__ unsigned g_rel[2];             // barrier release generations (monotone)

// ---------------------------------------------------------------------------
// Grid barrier (generation-based, graph-replay-safe). Slot 0: 512 reduce
// blocks (zero-smem kernel, 4/SM -> co-resident). Slot 1: 128 tail blocks
// (192KB smem, 1/SM, 128 <= 148 -> co-resident).
// ---------------------------------------------------------------------------
template <int GRID_N>
__device__ __forceinline__ void grid_bar(int i) {
    __syncthreads();
    if (threadIdx.x == 0) {
        volatile unsigned* rel = &g_rel[i];
        const unsigned gen = *rel;          // read BEFORE our arrive
        __threadfence();                    // publish this block's phase writes
        if (atomicAdd(&g_cnt[i], 1u) == GRID_N - 1) {
            g_cnt[i] = 0;                   // reset for next graph replay
            __threadfence();
            atomicAdd(&g_rel[i], 1u);       // release (monotone)
        } else {
            while (*rel == gen) { __nanosleep(32); }
        }
        __threadfence();
    }
    __syncthreads();
}

// ---------------------------------------------------------------------------
// helpers
// ---------------------------------------------------------------------------
__device__ __forceinline__ void ffma2(unsigned long long& d,
                                      unsigned long long a,
                                      unsigned long long b) {
    asm("fma.rn.f32x2 %0, %1, %2, %0;" : "+l"(d) : "l"(a), "l"(b));
}
__device__ __forceinline__ void lds128(unsigned long long& lo,
                                       unsigned long long& hi,
                                       unsigned addr) {
    asm volatile("ld.shared.v2.u64 {%0, %1}, [%2];"
                 : "=l"(lo), "=l"(hi) : "r"(addr));
}
__device__ __forceinline__ float hsum2(unsigned long long v) {
    float2 f;
    __builtin_memcpy(&f, &v, 8);
    return f.x + f.y;
}
__device__ __forceinline__ float4 ldcs4(const float4* p) {   // streaming load
    float4 v;
    asm volatile("ld.global.cs.v4.f32 {%0,%1,%2,%3}, [%4];"
                 : "=f"(v.x), "=f"(v.y), "=f"(v.z), "=f"(v.w) : "l"(p));
    return v;
}
__device__ __forceinline__ void cp16(unsigned smem_addr, const void* gptr) {
    asm volatile("cp.async.cg.shared.global [%0], [%1], 16;"
                 :: "r"(smem_addr), "l"(gptr));
}
#define CP_COMMIT() asm volatile("cp.async.commit_group;")
#define CP_WAIT(N)  asm volatile("cp.async.wait_group %0;" :: "n"(N))

// ---------------------------------------------------------------------------
// Kernel 1: token-sum reduce — the R7-proven shape. 512 blocks, ZERO smem
// (the smem-carveout law: big smem halves streaming BW), 4-acc ldcs loop,
// in-kernel barrier + distributed fold16 -> g_xs.
// ---------------------------------------------------------------------------
__global__ void __launch_bounds__(256, 4) k_reduce(const float* __restrict__ x) {
    const int s = blockIdx.x & 15, b = blockIdx.x >> 4, j = threadIdx.x;
    {
        const float4* xp = reinterpret_cast<const float4*>(x)
                         + ((size_t)b * NT + (size_t)s * TOK) * ND4 + j;
        float4 a0 = make_float4(0.f, 0.f, 0.f, 0.f);
        float4 a1 = make_float4(0.f, 0.f, 0.f, 0.f);
        float4 a2 = make_float4(0.f, 0.f, 0.f, 0.f);
        float4 a3 = make_float4(0.f, 0.f, 0.f, 0.f);
        #pragma unroll 2
        for (int t = 0; t < TOK; t += 4) {
            float4 v0 = ldcs4(xp + (size_t)t * ND4);
            float4 v1 = ldcs4(xp + (size_t)(t + 1) * ND4);
            float4 v2 = ldcs4(xp + (size_t)(t + 2) * ND4);
            float4 v3 = ldcs4(xp + (size_t)(t + 3) * ND4);
            a0.x += v0.x; a0.y += v0.y; a0.z += v0.z; a0.w += v0.w;
            a1.x += v1.x; a1.y += v1.y; a1.z += v1.z; a1.w += v1.w;
            a2.x += v2.x; a2.y += v2.y; a2.z += v2.z; a2.w += v2.w;
            a3.x += v3.x; a3.y += v3.y; a3.z += v3.z; a3.w += v3.w;
        }
        float4 r = make_float4(a0.x + a1.x + a2.x + a3.x,
                               a0.y + a1.y + a2.y + a3.y,
                               a0.z + a1.z + a2.z + a3.z,
                               a0.w + a1.w + a2.w + a3.w);
        reinterpret_cast<float4*>(g_part[s])[b * ND4 + j] = r;
    }
    grid_bar<RGRID>(0);
    // fold16 -> g_xs: 8192 float4 over 512 blocks = 16 per block
    if (j < 16) {
        const int i = blockIdx.x * 16 + j;
        float4 v = make_float4(0.f, 0.f, 0.f, 0.f);
        #pragma unroll
        for (int s2 = 0; s2 < TS; ++s2) {
            float4 u = reinterpret_cast<const float4*>(g_part[s2])[i];
            v.x += u.x; v.y += u.y; v.z += u.z; v.w += u.w;
        }
        reinterpret_cast<float4*>(g_xs)[i] = v;
    }
}

// ---------------------------------------------------------------------------
// Tail building blocks.
// Layouts (16B slots):
//   As[d4][(b + d4) & 31]          : 256 x 32 slots = 128 KB
//   Ws[d4][(o + d4) & 7]           : 256 x 8 slots  =  32 KB
// Both compute-load conflict-free; stores <=4-way.
// ---------------------------------------------------------------------------

// Stage A (32 rows x full K) from gmem into swizzled smem. LDG coalesced.
__device__ __forceinline__ void stage_A(const float* __restrict__ src,
                                        float4* As) {
    const int tid = threadIdx.x;
    #pragma unroll 8
    for (int k = 0; k < 32; ++k) {
        const int idx = tid + k * 256;      // 0..8191
        const int b = idx >> 8, d4 = idx & 255;
        As[d4 * 32 + ((b + d4) & 31)] =
            reinterpret_cast<const float4*>(src)[b * ND4 + d4];
    }
}

// Prefetch one W o-stripe (8 rows x full K) via cp.async into swizzled smem.
__device__ __forceinline__ void stage_W_cp(const float* __restrict__ W,
                                           float4* Ws, int otile) {
    const int tid = threadIdx.x;
    const int o = tid >> 5, d0 = tid & 31;
    const unsigned base = (unsigned)__cvta_generic_to_shared(Ws);
    #pragma unroll
    for (int r = 0; r < 8; ++r) {
        const int d4 = d0 + r * 32;
        cp16(base + (unsigned)((d4 * 8 + ((o + d4) & 7)) << 4),
             reinterpret_cast<const float4*>(W) + (size_t)(otile + o) * ND4 + d4);
    }
}

// Full-K dot: thread (ox = tid&7, bb = tid>>3) computes one output.
__device__ __forceinline__ float dot_fullK(const float4* As, const float4* Ws) {
    const int tid = threadIdx.x;
    const int ox = tid & 7;
    const int bb = tid >> 3;
    const unsigned asBase = (unsigned)__cvta_generic_to_shared(As);
    const unsigned wsBase = (unsigned)__cvta_generic_to_shared(Ws);
    unsigned long long acc0 = 0ull, acc1 = 0ull;
    #pragma unroll 8
    for (int d4 = 0; d4 < 256; ++d4) {
        unsigned long long alo, ahi, wlo, whi;
        lds128(alo, ahi, asBase + (unsigned)((d4 * 32 + ((bb + d4) & 31)) << 4));
        lds128(wlo, whi, wsBase + (unsigned)((d4 * 8 + ((ox + d4) & 7)) << 4));
        ffma2(acc0, alo, wlo);
        ffma2(acc1, ahi, whi);
    }
    return hsum2(acc0) + hsum2(acc1);
}

// ---------------------------------------------------------------------------
// Kernel 2: tail. 128 blocks x 256 thr, 192 KB smem (1 block/SM).
// Full-K o-stripes: no K-split partials, no fold8, no epilogue, ONE barrier.
// ---------------------------------------------------------------------------
__global__ void __launch_bounds__(256) k_tail(const float* __restrict__ Wh,
                                              const float* __restrict__ Wp,
                                              const float* __restrict__ bias,
                                              float* __restrict__ out) {
    extern __shared__ float4 dynsm[];
    float4* Ws0 = dynsm;            // 2048 slots = 32 KB (Wh stripe)
    float4* Ws1 = dynsm + 2048;     // 2048 slots = 32 KB (Wp stripe)
    float4* As  = dynsm + 4096;     // 8192 slots = 128 KB (A, full K)
    const int tid = threadIdx.x;
    const int blk = blockIdx.x;
    const int otile = blk * OSTRIPE;
    const int ox = tid & 7;
    const int bb = tid >> 3;

    // Prefetch both W stripes: group0 = Wh (needed first), group1 = Wp.
    stage_W_cp(Wh, Ws0, otile);
    CP_COMMIT();
    stage_W_cp(Wp, Ws1, otile);
    CP_COMMIT();

    // Stage A = xs (full 128 KB, every block reads the same L2-hot data).
    stage_A(g_xs, As);
    CP_WAIT(1);                     // Wh stripe resident (Wp may be in flight)
    __syncthreads();

    // gemm0: xh[b, otile+ox] = <xs[b,:], Wh[otile+ox,:]>  — final, no K-split
    {
        const float r = dot_fullK(As, Ws0);
        g_xh[bb * ND + otile + ox] = r;
    }
    grid_bar<TGRID>(1);             // xh fully published

    // Re-stage A = xh, then gemm1 with bias fused.
    stage_A(g_xh, As);
    CP_WAIT(0);                     // Wp stripe resident
    __syncthreads();
    {
        const float r = dot_fullK(As, Ws1);
        out[bb * ND + otile + ox] = r + bias[otile + ox];
    }
}

// ---------------------------------------------------------------------------
extern "C" void kernel_launch(void* const* d_in, const int* in_sizes, int n_in,
                              void* d_out, int out_size) {
    const float* x  = (const float*)d_in[0];   // [32, 2048, 1024]
    const float* Wh = (const float*)d_in[1];   // [16, 64, 1024] -> flat [1024,1024]
    const float* Wp = (const float*)d_in[2];   // [1024, 1024]
    const float* bp = (const float*)d_in[3];   // [1024]
    float* out = (float*)d_out;                // [32, 1024]

    static int once = 0;
    if (!once) {
        cudaFuncSetAttribute(k_tail, cudaFuncAttributeMaxDynamicSharedMemorySize,
                             12288 * sizeof(float4));
        once = 1;
    }
    k_reduce<<<RGRID, 256>>>(x);
    k_tail<<<TGRID, 256, 12288 * sizeof(float4)>>>(Wh, Wp, bp, out);
}

// round 14
// speedup vs baseline: 1.2523x; 1.2006x over previous
#include <cuda_runtime.h>

#define NB 32      // batch
#define NT 2048    // tokens
#define ND 1024    // d_token == n_heads*d_head
#define ND4 (ND/4)
#define TS 16      // token splits in reduce
#define TOK (NT/TS)           // 128 tokens per reduce block
#define KS2 8      // GEMM K-splits (K-slice = 128 floats = 32 float4)
#define OT 64      // o-columns per GEMM block tile
#define RGRID 512  // reduce blocks (16 splits x 32 batch); 4/SM co-resident
#define TGRID 128  // tail blocks (16 o-tiles x 8 K-splits); co-resident

// Scratch (allocation-free: __device__ globals, zero-initialized)
__device__ float g_part[TS][NB * ND];     // reduce partials (2 MB)
__device__ float g_xs[NB * ND];           // folded token sum (128 KB)
__device__ float g_xc[KS2][NB * ND];      // GEMM1 K-split partials
__device__ float g_op[KS2][NB * ND];      // GEMM2 K-split partials
__device__ unsigned g_cnt[3];             // barrier arrive counters (self-reset)
__device__ unsigned g_rel[3];             // barrier release generations (monotone)

// ---------------------------------------------------------------------------
// Grid barrier (generation-based, graph-replay-safe). Slot 0: 512 reduce
// blocks (zero-smem kernel -> co-resident). Slots 1,2: 128 tail blocks.
// ---------------------------------------------------------------------------
template <int GRID_N>
__device__ __forceinline__ void grid_bar(int i) {
    __syncthreads();
    if (threadIdx.x == 0) {
        volatile unsigned* rel = &g_rel[i];
        const unsigned gen = *rel;          // read BEFORE our arrive
        __threadfence();                    // publish this block's phase writes
        if (atomicAdd(&g_cnt[i], 1u) == GRID_N - 1) {
            g_cnt[i] = 0;                   // reset for next graph replay
            __threadfence();
            atomicAdd(&g_rel[i], 1u);       // release (monotone)
        } else {
            while (*rel == gen) { __nanosleep(32); }
        }
        __threadfence();
    }
    __syncthreads();
}

// ---------------------------------------------------------------------------
// helpers
// ---------------------------------------------------------------------------
__device__ __forceinline__ void ffma2(unsigned long long& d,
                                      unsigned long long a,
                                      unsigned long long b) {
    asm("fma.rn.f32x2 %0, %1, %2, %0;" : "+l"(d) : "l"(a), "l"(b));
}
__device__ __forceinline__ void lds_v2u64(unsigned long long& lo,
                                          unsigned long long& hi,
                                          unsigned addr) {
    asm volatile("ld.shared.v2.u64 {%0, %1}, [%2];"
                 : "=l"(lo), "=l"(hi) : "r"(addr));
}
__device__ __forceinline__ float hsum2(unsigned long long v) {
    float2 f;
    __builtin_memcpy(&f, &v, 8);
    return f.x + f.y;
}
__device__ __forceinline__ float4 ldcs4(const float4* p) {   // streaming load
    float4 v;
    asm volatile("ld.global.cs.v4.f32 {%0,%1,%2,%3}, [%4];"
                 : "=f"(v.x), "=f"(v.y), "=f"(v.z), "=f"(v.w) : "l"(p));
    return v;
}
__device__ __forceinline__ void cp16(unsigned smem_addr, const void* gptr) {
    asm volatile("cp.async.cg.shared.global [%0], [%1], 16;"
                 :: "r"(smem_addr), "l"(gptr));
}
__device__ __forceinline__ void l2_prefetch(const void* p) {
    asm volatile("prefetch.global.L2 [%0];" :: "l"(p));
}
#define CP_COMMIT() asm volatile("cp.async.commit_group;")
#define CP_WAIT(N)  asm volatile("cp.async.wait_group %0;" :: "n"(N))

// ---------------------------------------------------------------------------
// Kernel 1: token-sum reduce (R7-proven: zero smem, 4-acc ldcs loop) + NEW:
// L2-prefetch of both weight matrices so the tail's cp.async hits L2, not
// DRAM. One 128B line per 2 threads covers all 8 MB; fire-and-forget.
// After the stream: grid barrier + distributed fold16 -> g_xs.
// ---------------------------------------------------------------------------
__global__ void __launch_bounds__(256, 4) k_reduce(const float* __restrict__ x,
                                                   const float* __restrict__ Wh,
                                                   const float* __restrict__ Wp) {
    const int s = blockIdx.x & 15, b = blockIdx.x >> 4, j = threadIdx.x;

    // ---- W L2 prefetch: 65536 lines of 128B across 131072 threads ----
    {
        const unsigned g = blockIdx.x * 256u + j;   // 0..131071
        if (g < 32768u)
            l2_prefetch(reinterpret_cast<const char*>(Wh) + (size_t)g * 128);
        else if (g < 65536u)
            l2_prefetch(reinterpret_cast<const char*>(Wp) + (size_t)(g - 32768u) * 128);
    }

    {
        const float4* xp = reinterpret_cast<const float4*>(x)
                         + ((size_t)b * NT + (size_t)s * TOK) * ND4 + j;
        float4 a0 = make_float4(0.f, 0.f, 0.f, 0.f);
        float4 a1 = make_float4(0.f, 0.f, 0.f, 0.f);
        float4 a2 = make_float4(0.f, 0.f, 0.f, 0.f);
        float4 a3 = make_float4(0.f, 0.f, 0.f, 0.f);
        #pragma unroll 2
        for (int t = 0; t < TOK; t += 4) {
            float4 v0 = ldcs4(xp + (size_t)t * ND4);
            float4 v1 = ldcs4(xp + (size_t)(t + 1) * ND4);
            float4 v2 = ldcs4(xp + (size_t)(t + 2) * ND4);
            float4 v3 = ldcs4(xp + (size_t)(t + 3) * ND4);
            a0.x += v0.x; a0.y += v0.y; a0.z += v0.z; a0.w += v0.w;
            a1.x += v1.x; a1.y += v1.y; a1.z += v1.z; a1.w += v1.w;
            a2.x += v2.x; a2.y += v2.y; a2.z += v2.z; a2.w += v2.w;
            a3.x += v3.x; a3.y += v3.y; a3.z += v3.z; a3.w += v3.w;
        }
        float4 r = make_float4(a0.x + a1.x + a2.x + a3.x,
                               a0.y + a1.y + a2.y + a3.y,
                               a0.z + a1.z + a2.z + a3.z,
                               a0.w + a1.w + a2.w + a3.w);
        reinterpret_cast<float4*>(g_part[s])[b * ND4 + j] = r;
    }
    grid_bar<RGRID>(0);
    // fold16 -> g_xs: 8192 float4 over 512 blocks = 16 per block
    if (j < 16) {
        const int i = blockIdx.x * 16 + j;
        float4 v = make_float4(0.f, 0.f, 0.f, 0.f);
        #pragma unroll
        for (int s2 = 0; s2 < TS; ++s2) {
            float4 u = reinterpret_cast<const float4*>(g_part[s2])[i];
            v.x += u.x; v.y += u.y; v.z += u.z; v.w += u.w;
        }
        reinterpret_cast<float4*>(g_xs)[i] = v;
    }
}

// ---------------------------------------------------------------------------
// GEMM compute core (proven R6-R12): As[b][d4] x Ws swizzled -> dst.
// 256 thr, tile 64o x 32b x 128K, f32x2 FFMA packed along K.
// ---------------------------------------------------------------------------
__device__ __forceinline__ void gemm_core(const float4* As, const float4* Ws,
                                          float* __restrict__ dst, int otile) {
    const int tid = threadIdx.x;
    const int ox = tid & 31;
    const int bp = tid >> 5;
    const unsigned asBase = (unsigned)__cvta_generic_to_shared(As);
    const unsigned wsBase = (unsigned)__cvta_generic_to_shared(Ws);

    unsigned long long acc[4][2];
    #pragma unroll
    for (int i = 0; i < 4; ++i) { acc[i][0] = 0ull; acc[i][1] = 0ull; }

    #pragma unroll 8
    for (int d4 = 0; d4 < 32; ++d4) {
        unsigned long long w0lo, w0hi, w1lo, w1hi;
        lds_v2u64(w0lo, w0hi, wsBase + (unsigned)((d4 * OT + ((ox + d4) & 63)) << 4));
        lds_v2u64(w1lo, w1hi, wsBase + (unsigned)((d4 * OT + ((ox + 32 + d4) & 63)) << 4));
        #pragma unroll
        for (int i = 0; i < 4; ++i) {
            unsigned long long alo, ahi;
            lds_v2u64(alo, ahi, asBase + (unsigned)((((4 * bp + i) * 32 + d4)) << 4));
            ffma2(acc[i][0], alo, w0lo);
            ffma2(acc[i][0], ahi, w0hi);
            ffma2(acc[i][1], alo, w1lo);
            ffma2(acc[i][1], ahi, w1hi);
        }
    }
    #pragma unroll
    for (int i = 0; i < 4; ++i) {
        const int b = 4 * bp + i;
        dst[b * ND + otile + ox]      = hsum2(acc[i][0]);
        dst[b * ND + otile + 32 + ox] = hsum2(acc[i][1]);
    }
}

// issue cp.async for one W tile (64o x 32d4, swizzled layout)
__device__ __forceinline__ void w_tile_cp(const float* __restrict__ W,
                                          float4* Ws, int otile, int kbase4) {
    const int tid = threadIdx.x;
    const int o = tid >> 5, d4 = tid & 31;
    const unsigned base = (unsigned)__cvta_generic_to_shared(Ws);
    #pragma unroll
    for (int r = 0; r < 8; ++r) {
        const int oo = o + r * 8;
        cp16(base + (unsigned)((d4 * OT + ((oo + d4) & 63)) << 4),
             reinterpret_cast<const float4*>(W) + (size_t)(otile + oo) * ND4 + kbase4 + d4);
    }
}

// ---------------------------------------------------------------------------
// Kernel 2: tail (R7-proven). 128 blocks x 256 thr, 80 KB dynamic smem.
// Prefetch: group0 = {Wh tile + xs A-tile}, group1 = {Wp tile} — now both
// L2-hot thanks to the reduce's prefetch.
// gemm0 -> bar -> fold8 + gemm1 -> bar -> epilogue.
// ---------------------------------------------------------------------------
__global__ void __launch_bounds__(256) k_tail(const float* __restrict__ Wh,
                                              const float* __restrict__ Wp,
                                              const float* __restrict__ bias,
                                              float* __restrict__ out) {
    extern __shared__ float4 dynsm[];
    float4* Ws0 = dynsm;            // 2048 float4 = 32 KB (Wh tile)
    float4* Ws1 = dynsm + 2048;     // 2048 float4 = 32 KB (Wp tile)
    float4* As  = dynsm + 4096;     // 1024 float4 = 16 KB
    const int tid = threadIdx.x;
    const int blk = blockIdx.x;
    const int otile  = (blk >> 3) * OT;
    const int kbase4 = (blk & 7) * 32;

    // group 0: Wh tile + A tile (xs K-slice) — needed for gemm0
    w_tile_cp(Wh, Ws0, otile, kbase4);
    {
        const unsigned base = (unsigned)__cvta_generic_to_shared(As);
        #pragma unroll
        for (int k = 0; k < 4; ++k) {
            const int idx = tid + k * 256;      // 1024 = 32b x 32d4
            const int b = idx >> 5, d4 = idx & 31;
            cp16(base + (unsigned)(idx << 4),
                 reinterpret_cast<const float4*>(g_xs) + b * ND4 + kbase4 + d4);
        }
    }
    CP_COMMIT();
    // group 1: Wp tile — needed only after the first barrier (latency hidden)
    w_tile_cp(Wp, Ws1, otile, kbase4);
    CP_COMMIT();

    CP_WAIT(1);          // group0 done; Wp may still be in flight
    __syncthreads();

    // Phase 1: gemm0 — g_xc[ks] = xs @ Wh^T
    gemm_core(As, Ws0, g_xc[blk & 7], otile);
    grid_bar<TGRID>(1);

    // Phase 2: fold8 A from g_xc, then gemm1 with prefetched Wp tile
    {
        #pragma unroll
        for (int k = 0; k < 4; ++k) {
            const int idx = tid + k * 256;
            const int b = idx >> 5, d4 = idx & 31;
            float4 v = make_float4(0.f, 0.f, 0.f, 0.f);
            #pragma unroll
            for (int p = 0; p < KS2; ++p) {
                float4 u = reinterpret_cast<const float4*>(g_xc[p])[b * ND4 + kbase4 + d4];
                v.x += u.x; v.y += u.y; v.z += u.z; v.w += u.w;
            }
            As[idx] = v;
        }
    }
    CP_WAIT(0);
    __syncthreads();
    gemm_core(As, Ws1, g_op[blk & 7], otile);
    grid_bar<TGRID>(2);

    // Phase 3: epilogue — out = fold(g_op,8) + bias (64 float4 / block)
    if (tid < 64) {
        const int i = blk * 64 + tid;
        const int c4 = i & (ND4 - 1);
        float4 acc = reinterpret_cast<const float4*>(bias)[c4];
        #pragma unroll
        for (int p = 0; p < KS2; ++p) {
            float4 v = reinterpret_cast<const float4*>(g_op[p])[i];
            acc.x += v.x; acc.y += v.y; acc.z += v.z; acc.w += v.w;
        }
        reinterpret_cast<float4*>(out)[i] = acc;
    }
}

// ---------------------------------------------------------------------------
extern "C" void kernel_launch(void* const* d_in, const int* in_sizes, int n_in,
                              void* d_out, int out_size) {
    const float* x  = (const float*)d_in[0];   // [32, 2048, 1024]
    const float* Wh = (const float*)d_in[1];   // [16, 64, 1024] -> flat [1024,1024]
    const float* Wp = (const float*)d_in[2];   // [1024, 1024]
    const float* bp = (const float*)d_in[3];   // [1024]
    float* out = (float*)d_out;                // [32, 1024]

    static int once = 0;
    if (!once) {
        cudaFuncSetAttribute(k_tail, cudaFuncAttributeMaxDynamicSharedMemorySize,
                             5120 * sizeof(float4));
        once = 1;
    }
    k_reduce<<<RGRID, 256>>>(x, Wh, Wp);
    k_tail<<<TGRID, 256, 5120 * sizeof(float4)>>>(Wh, Wp, bp, out);
}